// round 1
// baseline (speedup 1.0000x reference)
#include <cuda_runtime.h>
#include <cuda_bf16.h>
#include <math.h>

// Rigid-warp + trilinear resample of a 256^3 fp32 volume.
// Inputs (metadata order):
//   d_in[0] image_targ  [1,1,256,256,256] float32
//   d_in[1] rotation    [1,3] float32
//   d_in[2] translation [1,3] float32
//   d_in[3] ref_v2r     [4,4] float32
//   d_in[4] flo_v2r     [4,4] float32
// Output: [1,1,256,256,256] float32

#define DIMD 256
#define DIMH 256
#define DIMW 256

// Transform matrix (first 3 rows of the 4x4 voxel->voxel transform), computed
// on device by a tiny setup kernel.
__device__ float g_T[12];

__device__ __forceinline__ void matmul3(const float a[9], const float b[9], float c[9]) {
    #pragma unroll
    for (int i = 0; i < 3; i++)
        #pragma unroll
        for (int j = 0; j < 3; j++)
            c[i * 3 + j] = a[i * 3 + 0] * b[0 * 3 + j]
                         + a[i * 3 + 1] * b[1 * 3 + j]
                         + a[i * 3 + 2] * b[2 * 3 + j];
}

__device__ __forceinline__ void matmul4(const float a[16], const float b[16], float c[16]) {
    #pragma unroll
    for (int i = 0; i < 4; i++)
        #pragma unroll
        for (int j = 0; j < 4; j++)
            c[i * 4 + j] = a[i * 4 + 0] * b[0 * 4 + j]
                         + a[i * 4 + 1] * b[1 * 4 + j]
                         + a[i * 4 + 2] * b[2 * 4 + j]
                         + a[i * 4 + 3] * b[3 * 4 + j];
}

// General 4x4 inverse (MESA gluInvertMatrix). Works for row-major input since
// inv(M^T) = inv(M)^T.
__device__ void inv4(const float m[16], float invOut[16]) {
    float inv[16];

    inv[0]  =  m[5]*m[10]*m[15] - m[5]*m[11]*m[14] - m[9]*m[6]*m[15] +
               m[9]*m[7]*m[14]  + m[13]*m[6]*m[11] - m[13]*m[7]*m[10];
    inv[4]  = -m[4]*m[10]*m[15] + m[4]*m[11]*m[14] + m[8]*m[6]*m[15] -
               m[8]*m[7]*m[14]  - m[12]*m[6]*m[11] + m[12]*m[7]*m[10];
    inv[8]  =  m[4]*m[9]*m[15]  - m[4]*m[11]*m[13] - m[8]*m[5]*m[15] +
               m[8]*m[7]*m[13]  + m[12]*m[5]*m[11] - m[12]*m[7]*m[9];
    inv[12] = -m[4]*m[9]*m[14]  + m[4]*m[10]*m[13] + m[8]*m[5]*m[14] -
               m[8]*m[6]*m[13]  - m[12]*m[5]*m[10] + m[12]*m[6]*m[9];
    inv[1]  = -m[1]*m[10]*m[15] + m[1]*m[11]*m[14] + m[9]*m[2]*m[15] -
               m[9]*m[3]*m[14]  - m[13]*m[2]*m[11] + m[13]*m[3]*m[10];
    inv[5]  =  m[0]*m[10]*m[15] - m[0]*m[11]*m[14] - m[8]*m[2]*m[15] +
               m[8]*m[3]*m[14]  + m[12]*m[2]*m[11] - m[12]*m[3]*m[10];
    inv[9]  = -m[0]*m[9]*m[15]  + m[0]*m[11]*m[13] + m[8]*m[1]*m[15] -
               m[8]*m[3]*m[13]  - m[12]*m[1]*m[11] + m[12]*m[3]*m[9];
    inv[13] =  m[0]*m[9]*m[14]  - m[0]*m[10]*m[13] - m[8]*m[1]*m[14] +
               m[8]*m[2]*m[13]  + m[12]*m[1]*m[10] - m[12]*m[2]*m[9];
    inv[2]  =  m[1]*m[6]*m[15]  - m[1]*m[7]*m[14]  - m[5]*m[2]*m[15] +
               m[5]*m[3]*m[14]  + m[13]*m[2]*m[7]  - m[13]*m[3]*m[6];
    inv[6]  = -m[0]*m[6]*m[15]  + m[0]*m[7]*m[14]  + m[4]*m[2]*m[15] -
               m[4]*m[3]*m[14]  - m[12]*m[2]*m[7]  + m[12]*m[3]*m[6];
    inv[10] =  m[0]*m[5]*m[15]  - m[0]*m[7]*m[13]  - m[4]*m[1]*m[15] +
               m[4]*m[3]*m[13]  + m[12]*m[1]*m[7]  - m[12]*m[3]*m[5];
    inv[14] = -m[0]*m[5]*m[14]  + m[0]*m[6]*m[13]  + m[4]*m[1]*m[14] -
               m[4]*m[2]*m[13]  - m[12]*m[1]*m[6]  + m[12]*m[2]*m[5];
    inv[3]  = -m[1]*m[6]*m[11]  + m[1]*m[7]*m[10]  + m[5]*m[2]*m[11] -
               m[5]*m[3]*m[10]  - m[9]*m[2]*m[7]   + m[9]*m[3]*m[6];
    inv[7]  =  m[0]*m[6]*m[11]  - m[0]*m[7]*m[10]  - m[4]*m[2]*m[11] +
               m[4]*m[3]*m[10]  + m[8]*m[2]*m[7]   - m[8]*m[3]*m[6];
    inv[11] = -m[0]*m[5]*m[11]  + m[0]*m[7]*m[9]   + m[4]*m[1]*m[11] -
               m[4]*m[3]*m[9]   - m[8]*m[1]*m[7]   + m[8]*m[3]*m[5];
    inv[15] =  m[0]*m[5]*m[10]  - m[0]*m[6]*m[9]   - m[4]*m[1]*m[10] +
               m[4]*m[2]*m[9]   + m[8]*m[1]*m[6]   - m[8]*m[2]*m[5];

    float det = m[0]*inv[0] + m[1]*inv[4] + m[2]*inv[8] + m[3]*inv[12];
    det = 1.0f / det;
    #pragma unroll
    for (int i = 0; i < 16; i++) invOut[i] = inv[i] * det;
}

__global__ void compute_transform_kernel(const float* __restrict__ rot,
                                         const float* __restrict__ tra,
                                         const float* __restrict__ ref_v2r,
                                         const float* __restrict__ flo_v2r) {
    // single thread
    float cx = cosf(rot[0]), cy = cosf(rot[1]), cz = cosf(rot[2]);
    float sx = sinf(rot[0]), sy = sinf(rot[1]), sz = sinf(rot[2]);

    float Rx[9] = {1, 0, 0,
                   0, cx, -sx,
                   0, sx, cx};
    float Ry[9] = {cy, 0, sy,
                   0, 1, 0,
                   -sy, 0, cy};
    float Rz[9] = {cz, -sz, 0,
                   sz, cz, 0,
                   0, 0, 1};
    float RxRy[9], R[9];
    matmul3(Rx, Ry, RxRy);
    matmul3(RxRy, Rz, R);

    float Trig[16] = {
        R[0], R[1], R[2], tra[0],
        R[3], R[4], R[5], tra[1],
        R[6], R[7], R[8], tra[2],
        0.f,  0.f,  0.f,  1.f
    };

    float ref[16], flo[16];
    #pragma unroll
    for (int i = 0; i < 16; i++) { ref[i] = ref_v2r[i]; flo[i] = flo_v2r[i]; }

    float flo_inv[16], A[16], T[16];
    inv4(flo, flo_inv);
    matmul4(Trig, ref, A);
    matmul4(flo_inv, A, T);

    #pragma unroll
    for (int i = 0; i < 12; i++) g_T[i] = T[i];
}

__global__ void __launch_bounds__(256)
warp_trilinear_kernel(const float* __restrict__ X, float* __restrict__ out) {
    const int k = threadIdx.x;            // W (stride-1)
    const int j = blockIdx.x & (DIMH - 1);
    const int i = blockIdx.x >> 8;        // D

    // transform rows (L1-cached after first access)
    const float T00 = g_T[0], T01 = g_T[1], T02 = g_T[2],  T03 = g_T[3];
    const float T10 = g_T[4], T11 = g_T[5], T12 = g_T[6],  T13 = g_T[7];
    const float T20 = g_T[8], T21 = g_T[9], T22 = g_T[10], T23 = g_T[11];

    const float fi = (float)i, fj = (float)j, fk = (float)k;
    const float di = fmaf(T00, fi, fmaf(T01, fj, fmaf(T02, fk, T03)));
    const float dj = fmaf(T10, fi, fmaf(T11, fj, fmaf(T12, fk, T13)));
    const float dk = fmaf(T20, fi, fmaf(T21, fj, fmaf(T22, fk, T23)));

    const int idx = (i << 16) | (j << 8) | k;

    // strictly-interior mask (matches reference: >0 and <= dim-1)
    const bool ok = (di > 0.f) & (dj > 0.f) & (dk > 0.f) &
                    (di <= (float)(DIMD - 1)) &
                    (dj <= (float)(DIMH - 1)) &
                    (dk <= (float)(DIMW - 1));
    if (!ok) { out[idx] = 0.f; return; }

    const float fx = floorf(di), fy = floorf(dj), fz = floorf(dk);
    const float wcx = di - fx, wcy = dj - fy, wcz = dk - fz;
    const float wfx = 1.f - wcx, wfy = 1.f - wcy, wfz = 1.f - wcz;

    // ok => di in (0, 255], so x0 in [0,255]
    const int x0 = (int)fx, y0 = (int)fy, z0 = (int)fz;
    const int x1 = min(x0 + 1, DIMD - 1);
    const int y1 = min(y0 + 1, DIMH - 1);
    const int z1 = min(z0 + 1, DIMW - 1);

    const int bx0 = x0 << 16, bx1 = x1 << 16;
    const int by0 = y0 << 8,  by1 = y1 << 8;

    const float v000 = __ldg(X + (bx0 | by0 | z0));
    const float v001 = __ldg(X + (bx0 | by0 | z1));
    const float v010 = __ldg(X + (bx0 | by1 | z0));
    const float v011 = __ldg(X + (bx0 | by1 | z1));
    const float v100 = __ldg(X + (bx1 | by0 | z0));
    const float v101 = __ldg(X + (bx1 | by0 | z1));
    const float v110 = __ldg(X + (bx1 | by1 | z0));
    const float v111 = __ldg(X + (bx1 | by1 | z1));

    // interpolate along z, then y, then x
    const float c00 = fmaf(v000, wfz, v001 * wcz);
    const float c01 = fmaf(v010, wfz, v011 * wcz);
    const float c10 = fmaf(v100, wfz, v101 * wcz);
    const float c11 = fmaf(v110, wfz, v111 * wcz);

    const float c0 = fmaf(c00, wfy, c01 * wcy);
    const float c1 = fmaf(c10, wfy, c11 * wcy);

    out[idx] = fmaf(c0, wfx, c1 * wcx);
}

extern "C" void kernel_launch(void* const* d_in, const int* in_sizes, int n_in,
                              void* d_out, int out_size) {
    const float* image = (const float*)d_in[0];
    const float* rot   = (const float*)d_in[1];
    const float* tra   = (const float*)d_in[2];
    const float* refm  = (const float*)d_in[3];
    const float* flom  = (const float*)d_in[4];
    float* out = (float*)d_out;

    compute_transform_kernel<<<1, 1>>>(rot, tra, refm, flom);
    warp_trilinear_kernel<<<DIMD * DIMH, DIMW>>>(image, out);
}